// round 17
// baseline (speedup 1.0000x reference)
#include <cuda_runtime.h>
#include <cuda_bf16.h>
#include <cuda_fp16.h>
#include <cstdint>

// ---------------------------------------------------------------------------
// Mamba layer. R17: R16 (best, 243.2us) + two changes:
//   (1) G1 epilogue writes fp16 xp / fp16 gate directly (g_xr eliminated;
//       conv reads fp16 xp; ~70 MB less traffic).
//   (2) Scan TQ 16->32 (half the barrier epochs; 24 KB smem/block).
//   B=4, L=1024, D_MODEL=512, D_INNER=1024, D_STATE=16, D_CONV=4
// ---------------------------------------------------------------------------

typedef __half h16;

#define NB      4
#define NL      1024
#define DM      512
#define DI      1024
#define DS      16
#define M_ROWS  (NB*NL)          // 4096
#define NC2     1152             // padded: 1024 delta | 16 B | 16 C | 96 pad
#define TQ      32               // scan tile (timesteps)
#define NCH     8                // scan chunks
#define CHL     (NL/NCH)         // 128 steps per chunk
#define LOG2E   1.44269504f
#define CLP2    7.2134752f       // 5 * log2(e)

// fp32 scratch
__device__ float g_xc  [M_ROWS * DI];
__device__ float g_dbc [M_ROWS * NC2];
__device__ float g_o   [M_ROWS * DM];
__device__ float g_bc  [NC2];

// chunked-scan state: [chunk][b][i][s] flattened
#define CHST (NB * DI * DS)      // 65536 per chunk
__device__ float g_hl [NCH * CHST];
__device__ float g_ap [NCH * CHST];

// fp16 scratch
__device__ h16 g_xh  [M_ROWS * DM];      // clip(x)          (G1 A operand)
__device__ h16 g_xph [M_ROWS * DI];      // xp  (G1 out, conv in)
__device__ h16 g_gateh[M_ROWS * DI];     // silu(res) (G1 out, scan in)
__device__ h16 g_xch [M_ROWS * DI];      // xc  (G3 A operand)
__device__ h16 g_ygh [M_ROWS * DI];      // yg  (G4 A operand)
__device__ h16 g_w1h [2048 * DM];        // W_in^T  [2048,512]
__device__ h16 g_w3h [NC2 * DI];         // Wcomb^T [1152,1024]
__device__ h16 g_w4h [DM * DI];          // W_out^T [512,1024]

// ---------------------------------------------------------------------------
// helpers
// ---------------------------------------------------------------------------
__device__ __forceinline__ uint32_t s2u(const void* p) {
    uint32_t a;
    asm("{ .reg .u64 t; cvta.to.shared.u64 t, %1; cvt.u32.u64 %0, t; }"
        : "=r"(a) : "l"(p));
    return a;
}

__device__ __forceinline__ float ex2f(float x) {
    float r;
    asm("ex2.approx.f32 %0, %1;" : "=f"(r) : "f"(x));
    return r;
}

__device__ __forceinline__ void cp16(uint32_t dst, const void* src) {
    asm volatile("cp.async.cg.shared.global [%0], [%1], 16;"
                 :: "r"(dst), "l"(src));
}
__device__ __forceinline__ void cp_commit() {
    asm volatile("cp.async.commit_group;");
}
template<int N> __device__ __forceinline__ void cp_wait() {
    asm volatile("cp.async.wait_group %0;" :: "n"(N));
}

__device__ __forceinline__ void ldmx4(uint32_t* r, uint32_t addr) {
    asm volatile("ldmatrix.sync.aligned.m8n8.x4.shared.b16 {%0,%1,%2,%3}, [%4];"
                 : "=r"(r[0]), "=r"(r[1]), "=r"(r[2]), "=r"(r[3]) : "r"(addr));
}

__device__ __forceinline__ void mma16816h(float* c, const uint32_t* a,
                                          uint32_t b0, uint32_t b1) {
    asm volatile(
        "mma.sync.aligned.m16n8k16.row.col.f32.f16.f16.f32 "
        "{%0,%1,%2,%3}, {%4,%5,%6,%7}, {%8,%9}, {%0,%1,%2,%3};"
        : "+f"(c[0]), "+f"(c[1]), "+f"(c[2]), "+f"(c[3])
        : "r"(a[0]), "r"(a[1]), "r"(a[2]), "r"(a[3]), "r"(b0), "r"(b1));
}

// ---------------------------------------------------------------------------
// fp16 MMA GEMM (128x128 CTA tile): BK=64, 8 warps (2x4), warp tile 64x32,
// 2-stage cp.async. MODE: 0 = fp32 store, 1 = fp32 store + bias,
//                         2 = G1 epilogue (fp16 xp / fp16 silu(res) split).
// ---------------------------------------------------------------------------
#define RPITCH      144                       // bytes per 64-elem row
#define MAT_BYTES   (128 * RPITCH)            // 18432
#define STAGE_BYTES (2 * MAT_BYTES)           // 36864
#define GEMM_SMEM   (2 * STAGE_BYTES)         // 73728

__device__ __forceinline__ void load_mat(const h16* __restrict__ g,
                                         int base_row, int K, int k0,
                                         uint32_t dst, int tid) {
    #pragma unroll
    for (int it = 0; it < 4; ++it) {
        int j = tid + it * 256;                 // 0..1023
        int r = j >> 3;                         // 0..127
        int c = j & 7;                          // 16B chunk (8 per 128B row)
        cp16(dst + r * RPITCH + c * 16,
             g + (size_t)(base_row + r) * K + k0 + c * 8);
    }
}

template<int MODE>
__global__ __launch_bounds__(256)
void mmagemm_kernel(const h16* __restrict__ A, const h16* __restrict__ B,
                    const float* __restrict__ bias, float* __restrict__ C,
                    int K, int ldc)
{
    extern __shared__ char smem[];
    const uint32_t sb = s2u(smem);
    const int tid  = threadIdx.x;
    const int wid  = tid >> 5;
    const int lane = tid & 31;
    const int row0 = blockIdx.y * 128;
    const int col0 = blockIdx.x * 128;
    const int row_w = (wid & 1) * 64;
    const int col_w = (wid >> 1) * 32;

    float acc[4][4][4] = {};

    const int nchunk = K >> 6;

    load_mat(A, row0, K, 0, sb + 0,         tid);
    load_mat(B, col0, K, 0, sb + MAT_BYTES, tid);
    cp_commit();

    const int lrow = lane & 15;
    const int lhal = (lane >> 4) & 1;

    for (int i = 0; i < nchunk; ++i) {
        const uint32_t st = sb + (uint32_t)(i & 1) * STAGE_BYTES;
        if (i + 1 < nchunk) {
            const uint32_t nt = sb + (uint32_t)((i + 1) & 1) * STAGE_BYTES;
            load_mat(A, row0, K, (i + 1) * 64, nt + 0,         tid);
            load_mat(B, col0, K, (i + 1) * 64, nt + MAT_BYTES, tid);
            cp_commit();
            cp_wait<1>();
        } else {
            cp_wait<0>();
        }
        __syncthreads();

        #pragma unroll
        for (int ks = 0; ks < 4; ++ks) {
            uint32_t ah[4][4], bh[2][4];
            const uint32_t koff = ks * 32 + lhal * 16;
            #pragma unroll
            for (int mb = 0; mb < 4; ++mb) {
                const uint32_t ra = (row_w + mb * 16 + lrow) * RPITCH + koff;
                ldmx4(ah[mb], st + ra);
            }
            #pragma unroll
            for (int nb2 = 0; nb2 < 2; ++nb2) {
                const uint32_t rb = (col_w + nb2 * 16 + lrow) * RPITCH + koff;
                ldmx4(bh[nb2], st + MAT_BYTES + rb);
            }
            #pragma unroll
            for (int mb = 0; mb < 4; ++mb) {
                #pragma unroll
                for (int nb2 = 0; nb2 < 2; ++nb2) {
                    #pragma unroll
                    for (int hf = 0; hf < 2; ++hf) {
                        mma16816h(acc[mb][nb2 * 2 + hf], ah[mb],
                                  bh[nb2][hf], bh[nb2][hf + 2]);
                    }
                }
            }
        }
        __syncthreads();
    }

    const int g   = lane >> 2;
    const int tig = lane & 3;
    #pragma unroll
    for (int mb = 0; mb < 4; ++mb) {
        #pragma unroll
        for (int nb = 0; nb < 4; ++nb) {
            const int col = col0 + col_w + nb * 8 + tig * 2;
            const int r0  = row0 + row_w + mb * 16 + g;
            float* c = acc[mb][nb];
            if (MODE == 2) {
                // G1 split epilogue: col < 1024 -> xp fp16; else silu -> gate fp16
                #pragma unroll
                for (int hrow = 0; hrow < 2; ++hrow) {
                    const int r = r0 + hrow * 8;
                    float v0 = c[hrow * 2 + 0], v1 = c[hrow * 2 + 1];
                    if (col < DI) {
                        __half2 hv = __floats2half2_rn(v0, v1);
                        *(__half2*)&g_xph[(size_t)r * DI + col] = hv;
                    } else {
                        float s0 = v0 / (1.f + __expf(-v0));
                        float s1 = v1 / (1.f + __expf(-v1));
                        __half2 hv = __floats2half2_rn(s0, s1);
                        *(__half2*)&g_gateh[(size_t)r * DI + (col - DI)] = hv;
                    }
                }
            } else {
                float2 v0 = make_float2(c[0], c[1]);
                float2 v1 = make_float2(c[2], c[3]);
                if (MODE == 1) {
                    const float b0 = bias[col], b1 = bias[col + 1];
                    v0.x += b0; v0.y += b1;
                    v1.x += b0; v1.y += b1;
                }
                *(float2*)&C[(size_t)r0 * ldc + col]       = v0;
                *(float2*)&C[(size_t)(r0 + 8) * ldc + col] = v1;
            }
        }
    }
}

// ---------------------------------------------------------------------------
// fused prep kernel: one launch, segmented grid; all segments run in parallel.
// ---------------------------------------------------------------------------
#define PREP_BLOCKS (8192 + 1024 + 1024 + 32 + 512 + 384 + 5)

__global__ __launch_bounds__(256)
void prep_kernel(const float* __restrict__ x,
                 const float* __restrict__ W_in,
                 const float* __restrict__ W_dt,
                 const float* __restrict__ W_x,
                 const float* __restrict__ W_out,
                 const float* __restrict__ b_dt)
{
    __shared__ float t[32][33];
    int bid = blockIdx.x;
    const int tid = threadIdx.x;

    if (bid < 8192) {                       // S0: clip(x) -> fp16
        int idx = bid * 256 + tid;
        float v = fminf(fmaxf(x[idx], -10.f), 10.f);
        g_xh[idx] = __float2half_rn(v);
        return;
    }
    bid -= 8192;

    const float* src; h16* dst;
    int N, ldk, ro;
    if (bid < 1024)      { src = W_in;  N = 2048; dst = g_w1h; ldk = 512;  ro = 0; }
    else if (bid < 2048) { bid -= 1024; src = W_dt;  N = 1024; dst = g_w3h; ldk = 1024; ro = 0; }
    else if (bid < 2080) { bid -= 2048; src = W_x;   N = 32;   dst = g_w3h; ldk = 1024; ro = 1024; }
    else if (bid < 2592) { bid -= 2080; src = W_out; N = 512;  dst = g_w4h; ldk = 1024; ro = 0; }
    else if (bid < 2976) {                  // S5: zpad w3 rows [1056,1152)
        int idx = (bid - 2592) * 256 + tid;
        g_w3h[(size_t)1056 * DI + idx] = __float2half_rn(0.f);
        return;
    } else {                                // S6: bias
        int idx = (bid - 2976) * 256 + tid;
        if (idx < NC2) g_bc[idx] = (idx < DI) ? b_dt[idx] : 0.f;
        return;
    }

    const int ntx = N >> 5;
    const int bx  = bid % ntx, by = bid / ntx;
    const int k0  = by * 32, n0 = bx * 32;
    const int tx  = tid & 31, ty = tid >> 5;
    #pragma unroll
    for (int r = ty; r < 32; r += 8)
        t[r][tx] = src[(size_t)(k0 + r) * N + n0 + tx];
    __syncthreads();
    #pragma unroll
    for (int r = ty; r < 32; r += 8) {
        float v = t[tx][r];
        dst[(size_t)(ro + n0 + r) * ldk + k0 + tx] = __float2half_rn(v);
    }
}

// ---------------------------------------------------------------------------
// depthwise causal conv + bias + SiLU -> g_xc (fp32) + g_xch (fp16).
// Reads fp16 xp (G1 epilogue output).
// ---------------------------------------------------------------------------
__global__ void conv_silu_kernel(const float* __restrict__ conv_w,
                                 const float* __restrict__ conv_b)
{
    int idx = blockIdx.x * 256 + threadIdx.x;
    int i = idx & (DI - 1);
    int m = idx >> 10;
    int l = m & (NL - 1);

    float4 w = ((const float4*)conv_w)[i];
    float acc = conv_b[i];
    if (l >= 3) acc = fmaf(w.x, __half2float(g_xph[(size_t)(m - 3) * DI + i]), acc);
    if (l >= 2) acc = fmaf(w.y, __half2float(g_xph[(size_t)(m - 2) * DI + i]), acc);
    if (l >= 1) acc = fmaf(w.z, __half2float(g_xph[(size_t)(m - 1) * DI + i]), acc);
    acc = fmaf(w.w, __half2float(g_xph[(size_t)m * DI + i]), acc);

    float sig = 1.f / (1.f + __expf(-acc));
    float xc = acc * sig;
    g_xc[idx]  = xc;
    g_xch[idx] = __float2half_rn(xc);
}

// ---------------------------------------------------------------------------
// Chunked selective scan (16 thr/channel, 1 state/thread), TQ=32.
//   ud_s: (u, d, gate, -) float4; bc_s: (B, C) float2.
//   exp in exp2 domain via ex2.approx.
//   PASS 0: per-chunk scan from h=0; store (h_local, A_prod); last chunk's
//           state unused -> early exit.
//   PASS 1: inline combine of prior chunks -> h_in, re-scan, emit y (fp16).
// Grid = 4*64*8 = 2048 blocks.
// ---------------------------------------------------------------------------
template<int PASS>
__global__ __launch_bounds__(256)
void scan_pass_kernel(const float* __restrict__ A_log,
                      const float* __restrict__ D_skip)
{
    __shared__ float4 ud_s[2][TQ][16];      // (u, d, gate, -)
    __shared__ float2 bc_s[2][TQ][16];      // (B, C)

    const int chunk = blockIdx.x & (NCH - 1);
    if (PASS == 0 && chunk == NCH - 1) return;      // state never consumed

    const int tid = threadIdx.x;
    const int c   = tid >> 4;
    const int s   = tid & 15;
    const int b     = blockIdx.x >> 9;
    const int itile = (blockIdx.x >> 3) & 63;
    const int i_base = itile << 4;
    const int i   = i_base + c;
    const int mb  = b * NL + chunk * CHL;

    const float ALs2 = A_log[s] * LOG2E;
    const float Dsk = D_skip[i];

    // cooperative load mapping: thread (lt, lc); each thread stages 2 steps
    const int lc = tid & 15;
    const int lt = tid >> 4;

    float ru[2], rd[2], rg[2], rB[2], rC[2];

    #define LOAD_TILE(tile) do {                                              \
        _Pragma("unroll")                                                     \
        for (int hh = 0; hh < 2; ++hh) {                                      \
            int m = mb + (tile) * TQ + hh * 16 + lt;                          \
            ru[hh] = g_xc [(size_t)m * DI  + i_base + lc];                    \
            rd[hh] = g_dbc[(size_t)m * NC2 + i_base + lc];                    \
            if (PASS == 1)                                                    \
                rg[hh] = __half2float(g_gateh[(size_t)m * DI + i_base + lc]); \
            rB[hh] = g_dbc[(size_t)m * NC2 + 1024 + lc];                      \
            rC[hh] = g_dbc[(size_t)m * NC2 + 1040 + lc];                      \
        }                                                                     \
    } while (0)

    #define STS_TILE(buf) do {                                                \
        _Pragma("unroll")                                                     \
        for (int hh = 0; hh < 2; ++hh) {                                      \
            ud_s[buf][hh * 16 + lt][lc] =                                     \
                make_float4(ru[hh], rd[hh], (PASS == 1) ? rg[hh] : 0.f, 0.f); \
            bc_s[buf][hh * 16 + lt][lc] = make_float2(rB[hh], rC[hh]);        \
        }                                                                     \
    } while (0)

    LOAD_TILE(0);
    STS_TILE(0);

    const int sidx0 = b * (DI * DS) + i * DS + s;
    float h = 0.f, ap;
    if (PASS == 0) {
        ap = 1.f;
    } else {
        for (int ch = 0; ch < chunk; ++ch) {
            int o = ch * CHST + sidx0;
            h = fmaf(g_ap[o], h, g_hl[o]);
        }
    }
    __syncthreads();

    const unsigned fm = 0xffffffffu;
    const int NT = CHL / TQ;                        // 4 tiles per chunk

    for (int tile = 0; tile < NT; ++tile) {
        const int cur = tile & 1, nxt = cur ^ 1;
        if (tile + 1 < NT) LOAD_TILE(tile + 1);

        #pragma unroll
        for (int tt = 0; tt < TQ; ++tt) {
            float4 ud = ud_s[cur][tt][c];
            float2 bc = bc_s[cur][tt][s];

            float a2 = fminf(fmaxf(ud.y * ALs2, -CLP2), CLP2);
            float dA = ex2f(a2);
            if (PASS == 0) ap *= dA;
            h = fmaf(dA, h, (ud.y * ud.x) * bc.x);

            if (PASS == 1) {
                float p = h * bc.y;
                p += __shfl_xor_sync(fm, p, 1);
                p += __shfl_xor_sync(fm, p, 2);
                p += __shfl_xor_sync(fm, p, 4);
                p += __shfl_xor_sync(fm, p, 8);

                if (s == 0) {
                    int m = mb + tile * TQ + tt;
                    float v = fmaf(ud.x, Dsk, p) * ud.z;
                    g_ygh[(size_t)m * DI + i] = __float2half_rn(v);
                }
            }
        }

        if (tile + 1 < NT) STS_TILE(nxt);
        __syncthreads();
    }

    if (PASS == 0) {
        int o = chunk * CHST + sidx0;
        g_hl[o] = h;
        g_ap[o] = ap;
    }
    #undef LOAD_TILE
    #undef STS_TILE
}

// ---------------------------------------------------------------------------
// residual + layernorm.  one warp per row (512 cols).
// ---------------------------------------------------------------------------
__global__ __launch_bounds__(256)
void ln_kernel(const float* __restrict__ x,
               const float* __restrict__ gamma,
               const float* __restrict__ beta,
               float* __restrict__ out)
{
    const int w = threadIdx.x >> 5;
    const int lane = threadIdx.x & 31;
    const int row = blockIdx.x * 8 + w;

    const float4* orow = (const float4*)&g_o[(size_t)row * DM];
    const float4* xrow = (const float4*)&x[(size_t)row * DM];

    float vals[16];
    float sum = 0.f, sq = 0.f;
    #pragma unroll
    for (int j = 0; j < 4; ++j) {
        float4 o = orow[lane + j * 32];
        float4 xv = xrow[lane + j * 32];
        float r0 = o.x + fminf(fmaxf(xv.x, -10.f), 10.f);
        float r1 = o.y + fminf(fmaxf(xv.y, -10.f), 10.f);
        float r2 = o.z + fminf(fmaxf(xv.z, -10.f), 10.f);
        float r3 = o.w + fminf(fmaxf(xv.w, -10.f), 10.f);
        vals[j * 4 + 0] = r0; vals[j * 4 + 1] = r1;
        vals[j * 4 + 2] = r2; vals[j * 4 + 3] = r3;
        sum += r0 + r1 + r2 + r3;
        sq  += r0 * r0 + r1 * r1 + r2 * r2 + r3 * r3;
    }
    #pragma unroll
    for (int off = 16; off >= 1; off >>= 1) {
        sum += __shfl_xor_sync(0xffffffffu, sum, off);
        sq  += __shfl_xor_sync(0xffffffffu, sq,  off);
    }
    const float mean = sum * (1.f / DM);
    const float var  = sq * (1.f / DM) - mean * mean;
    const float rstd = rsqrtf(var + 1e-5f);

    #pragma unroll
    for (int j = 0; j < 4; ++j) {
        float4 gm = ((const float4*)gamma)[lane + j * 32];
        float4 bt = ((const float4*)beta)[lane + j * 32];
        float4 o;
        o.x = fmaf((vals[j*4+0] - mean) * rstd, gm.x, bt.x);
        o.y = fmaf((vals[j*4+1] - mean) * rstd, gm.y, bt.y);
        o.z = fmaf((vals[j*4+2] - mean) * rstd, gm.z, bt.z);
        o.w = fmaf((vals[j*4+3] - mean) * rstd, gm.w, bt.w);
        ((float4*)&out[(size_t)row * DM])[lane + j * 32] = o;
    }
}

// ---------------------------------------------------------------------------
extern "C" void kernel_launch(void* const* d_in, const int* in_sizes, int n_in,
                              void* d_out, int out_size)
{
    const float* x      = (const float*)d_in[0];
    const float* W_in   = (const float*)d_in[1];
    const float* conv_w = (const float*)d_in[2];
    const float* conv_b = (const float*)d_in[3];
    const float* W_x    = (const float*)d_in[4];
    const float* W_dt   = (const float*)d_in[5];
    const float* b_dt   = (const float*)d_in[6];
    const float* A_log  = (const float*)d_in[7];
    const float* D_skip = (const float*)d_in[8];
    const float* W_out  = (const float*)d_in[9];
    const float* gamma  = (const float*)d_in[10];
    const float* beta   = (const float*)d_in[11];
    float* out = (float*)d_out;

    cudaFuncSetAttribute(mmagemm_kernel<0>,
                         cudaFuncAttributeMaxDynamicSharedMemorySize, GEMM_SMEM);
    cudaFuncSetAttribute(mmagemm_kernel<1>,
                         cudaFuncAttributeMaxDynamicSharedMemorySize, GEMM_SMEM);
    cudaFuncSetAttribute(mmagemm_kernel<2>,
                         cudaFuncAttributeMaxDynamicSharedMemorySize, GEMM_SMEM);

    void *p_dbc, *p_o, *p_bc;
    void *p_xh, *p_xch, *p_ygh, *p_w1h, *p_w3h, *p_w4h;
    cudaGetSymbolAddress(&p_dbc, g_dbc);
    cudaGetSymbolAddress(&p_o,   g_o);
    cudaGetSymbolAddress(&p_bc,  g_bc);
    cudaGetSymbolAddress(&p_xh,  g_xh);
    cudaGetSymbolAddress(&p_xch, g_xch);
    cudaGetSymbolAddress(&p_ygh, g_ygh);
    cudaGetSymbolAddress(&p_w1h, g_w1h);
    cudaGetSymbolAddress(&p_w3h, g_w3h);
    cudaGetSymbolAddress(&p_w4h, g_w4h);

    // fused operand prep (clip+cvt x, transpose+cvt weights, zpad, bias)
    prep_kernel<<<PREP_BLOCKS, 256>>>(x, W_in, W_dt, W_x, W_out, b_dt);

    // G1: [xp | res] = clip(x) @ W_in, epilogue -> fp16 xp + fp16 silu(res)
    {
        dim3 grid(2048 / 128, M_ROWS / 128);
        mmagemm_kernel<2><<<grid, 256, GEMM_SMEM>>>(
            (const h16*)p_xh, (const h16*)p_w1h,
            nullptr, nullptr, DM, 0);
    }

    // conv + silu -> xc (fp32 + fp16)
    conv_silu_kernel<<<(M_ROWS * DI) / 256, 256>>>(conv_w, conv_b);

    // G3: dbc = xc @ Wcomb + bcomb   [4096 x 1152], K=1024
    {
        dim3 grid(NC2 / 128, M_ROWS / 128);
        mmagemm_kernel<1><<<grid, 256, GEMM_SMEM>>>(
            (const h16*)p_xch, (const h16*)p_w3h,
            (const float*)p_bc, (float*)p_dbc, DI, NC2);
    }

    // chunked selective scan: pass 0 (local, 7/8 chunks), pass 1 (combine + emit)
    scan_pass_kernel<0><<<NB * 64 * NCH, 256>>>(A_log, D_skip);
    scan_pass_kernel<1><<<NB * 64 * NCH, 256>>>(A_log, D_skip);

    // G4: o = yg @ W_out   [4096 x 512], K=1024
    {
        dim3 grid(DM / 128, M_ROWS / 128);
        mmagemm_kernel<0><<<grid, 256, GEMM_SMEM>>>(
            (const h16*)p_ygh, (const h16*)p_w4h,
            nullptr, (float*)p_o, DI, DM);
    }

    // residual + layernorm -> out
    ln_kernel<<<M_ROWS / 8, 256>>>(x, gamma, beta, out);
}